// round 9
// baseline (speedup 1.0000x reference)
#include <cuda_runtime.h>
#include <cuda_fp16.h>
#include <math.h>
#include <stdint.h>

// ---------------- problem constants ----------------
#define BATCH   32
#define HW      56
#define DIM     256
#define WS      7
#define SHIFT   3
#define NH      8
#define HD      32
#define NTOK    49
#define NWIN    64
#define BW      (BATCH*NWIN)
#define MTOK    (BATCH*HW*HW)   // 100352
#define SCALE   0.17677669529663687f

// ---------------- scratch ----------------
__device__ __half hb_a  [(size_t)MTOK * 256];
__device__ __half hb_qkv[(size_t)MTOK * 768];
__device__ __half hb_h1 [(size_t)MTOK * 1024];
__device__ float  g_xres[(size_t)MTOK * 256];
__device__ float  g_bias[NH * NTOK * NTOK];
__device__ __half hw_qkv [768 * 256];
__device__ __half hw_proj[256 * 256];
__device__ __half hw_fc1 [1024 * 256];
__device__ __half hw_fc2 [256 * 1024];

// ---------------- PTX helpers ----------------
__device__ __forceinline__ uint32_t cvta_s(const void* p) {
    uint32_t a;
    asm("{ .reg .u64 t; cvta.to.shared.u64 t, %1; cvt.u32.u64 %0, t; }" : "=r"(a) : "l"(p));
    return a;
}
__device__ __forceinline__ void ldsm_x4(unsigned* r, uint32_t a) {
    asm volatile("ldmatrix.sync.aligned.m8n8.x4.shared.b16 {%0,%1,%2,%3}, [%4];"
        : "=r"(r[0]), "=r"(r[1]), "=r"(r[2]), "=r"(r[3]) : "r"(a));
}
__device__ __forceinline__ void ldsm_x2(unsigned* r, uint32_t a) {
    asm volatile("ldmatrix.sync.aligned.m8n8.x2.shared.b16 {%0,%1}, [%2];"
        : "=r"(r[0]), "=r"(r[1]) : "r"(a));
}
#define CP_ASYNC16(dst, src) asm volatile("cp.async.ca.shared.global [%0], [%1], 16;" :: "r"(dst), "l"(src))
#define CP_COMMIT()          asm volatile("cp.async.commit_group;" ::: "memory")
#define CP_WAIT2()           asm volatile("cp.async.wait_group 2;" ::: "memory")
#define CP_WAIT1()           asm volatile("cp.async.wait_group 1;" ::: "memory")
#define CP_WAIT0()           asm volatile("cp.async.wait_group 0;" ::: "memory")

__device__ __forceinline__ void mma_f16(float* c, const unsigned* a, const unsigned* b) {
    asm("mma.sync.aligned.m16n8k16.row.col.f32.f16.f16.f32 "
        "{%0,%1,%2,%3},{%4,%5,%6,%7},{%8,%9},{%0,%1,%2,%3};"
        : "+f"(c[0]), "+f"(c[1]), "+f"(c[2]), "+f"(c[3])
        : "r"(a[0]), "r"(a[1]), "r"(a[2]), "r"(a[3]), "r"(b[0]), "r"(b[1]));
}

// ---------------- weight fp32 -> fp16 ----------------
__global__ void wconv_kernel(const float* __restrict__ w0, __half* __restrict__ o0, int n0,
                             const float* __restrict__ w1, __half* __restrict__ o1, int n1)
{
    int i = blockIdx.x * 256 + threadIdx.x;
    if (i < n0) o0[i] = __float2half(w0[i]);
    else if (i < n0 + n1) o1[i - n0] = __float2half(w1[i - n0]);
}

// ---------------- rel-pos bias ----------------
__global__ void bias_kernel(const float* __restrict__ rel_table, float* __restrict__ bias)
{
    int i = blockIdx.x * 256 + threadIdx.x;
    if (i >= NH * NTOK * NTOK) return;
    int h = i / (NTOK*NTOK), rem = i % (NTOK*NTOK);
    int n = rem / NTOK, m = rem % NTOK;
    int rn = n / 7, cn = n % 7, rm = m / 7, cm = m % 7;
    int idx = (rn - rm + 6) * 13 + (cn - cm + 6);
    bias[i] = rel_table[idx * NH + h];
}

// ---------------- LayerNorm: one row per warp, float4 I/O ----------------
template<int PERM>
__global__ void __launch_bounds__(256) ln_kernel(
    const float* __restrict__ in, __half* __restrict__ out,
    const float* __restrict__ gam, const float* __restrict__ bet)
{
    const int row = blockIdx.x * 8 + (threadIdx.x >> 5);
    const int lane = threadIdx.x & 31;
    int src;
    if (PERM) {
        int bw = row / NTOK, t = row % NTOK;
        int b = bw >> 6, w = bw & 63;
        int wh = w >> 3, ww = w & 7;
        int r = t / 7, c = t % 7;
        int gh = wh * 7 + r + SHIFT; if (gh >= HW) gh -= HW;
        int gw = ww * 7 + c + SHIFT; if (gw >= HW) gw -= HW;
        src = (b * (HW*HW) + gh * HW + gw) * DIM;
    } else {
        src = row * DIM;
    }
    const int col = lane * 8;
    float4 v0 = *(const float4*)&in[src + col];
    float4 v1 = *(const float4*)&in[src + col + 4];

    float s = v0.x+v0.y+v0.z+v0.w + v1.x+v1.y+v1.z+v1.w;
    float q = v0.x*v0.x+v0.y*v0.y+v0.z*v0.z+v0.w*v0.w
            + v1.x*v1.x+v1.y*v1.y+v1.z*v1.z+v1.w*v1.w;
    #pragma unroll
    for (int o = 16; o > 0; o >>= 1) {
        s += __shfl_xor_sync(0xFFFFFFFFu, s, o);
        q += __shfl_xor_sync(0xFFFFFFFFu, q, o);
    }
    float mu = s * (1.0f/DIM);
    float rstd = rsqrtf(q * (1.0f/DIM) - mu*mu + 1e-5f);

    float4 g0 = *(const float4*)&gam[col], g1 = *(const float4*)&gam[col+4];
    float4 b0 = *(const float4*)&bet[col], b1 = *(const float4*)&bet[col+4];

    uint4 o8;
    ((__half2*)&o8)[0] = __floats2half2_rn((v0.x-mu)*rstd*g0.x+b0.x, (v0.y-mu)*rstd*g0.y+b0.y);
    ((__half2*)&o8)[1] = __floats2half2_rn((v0.z-mu)*rstd*g0.z+b0.z, (v0.w-mu)*rstd*g0.w+b0.w);
    ((__half2*)&o8)[2] = __floats2half2_rn((v1.x-mu)*rstd*g1.x+b1.x, (v1.y-mu)*rstd*g1.y+b1.y);
    ((__half2*)&o8)[3] = __floats2half2_rn((v1.z-mu)*rstd*g1.z+b1.z, (v1.w-mu)*rstd*g1.w+b1.w);
    *(uint4*)&out[(size_t)row * DIM + col] = o8;
}

// ---------------- fp16 GEMM: cp.async 4-stage + ldmatrix, 1 sync/chunk ----
#define STG_H    (128 * 40)
#define STG_B    (STG_H * 2)
#define NSTG     4
#define GSMEM    (2 * NSTG * STG_B)   // 81920 B

template<int EPI>
__global__ void __launch_bounds__(256, 2) hgemm(
    const __half* __restrict__ A, const __half* __restrict__ B,
    const float* __restrict__ bias, float* __restrict__ Cf, __half* __restrict__ Ch,
    const float* __restrict__ res, int M, int Nn, int K)
{
    extern __shared__ __half dsm[];

    const int tid = threadIdx.x;
    const int lane = tid & 31, wid = tid >> 5;
    const int wm = wid >> 2, wn = wid & 3;
    const int gid = lane >> 2, tig = lane & 3;
    const int m0 = blockIdx.y * 128, n0 = blockIdx.x * 128;

    const uint32_t sbase = cvta_s(dsm);
    const uint32_t sA = sbase;
    const uint32_t sB = sbase + NSTG * STG_B;

    const int lr0 = tid >> 2, lq0 = (tid & 3);
    const int lr1 = lr0 + 64;

    float c[4][4][4];
    #pragma unroll
    for (int i = 0; i < 4; i++)
        #pragma unroll
        for (int j = 0; j < 4; j++)
            #pragma unroll
            for (int r = 0; r < 4; r++) c[i][j][r] = 0.f;

    const int nk = K >> 5;

    const uint32_t a_off = ((uint32_t)(wm * 64 + (lane & 15)) * 40 + (lane >> 4) * 8) * 2;
    const uint32_t b_off = ((uint32_t)(wn * 32 + (lane & 7)) * 40 + ((lane >> 3) & 1) * 8) * 2;

    auto issue = [&](int kt, int stg) {
        const size_t kb = (size_t)kt * 32 + lq0 * 8;
        uint32_t dA0 = sA + stg * STG_B + (lr0 * 40 + lq0 * 8) * 2;
        uint32_t dA1 = sA + stg * STG_B + (lr1 * 40 + lq0 * 8) * 2;
        uint32_t dB0 = sB + stg * STG_B + (lr0 * 40 + lq0 * 8) * 2;
        uint32_t dB1 = sB + stg * STG_B + (lr1 * 40 + lq0 * 8) * 2;
        CP_ASYNC16(dA0, &A[(size_t)(m0 + lr0) * K + kb]);
        CP_ASYNC16(dA1, &A[(size_t)(m0 + lr1) * K + kb]);
        CP_ASYNC16(dB0, &B[(size_t)(n0 + lr0) * K + kb]);
        CP_ASYNC16(dB1, &B[(size_t)(n0 + lr1) * K + kb]);
        CP_COMMIT();
    };

    issue(0, 0);
    if (nk > 1) issue(1, 1);
    if (nk > 2) issue(2, 2);

    for (int kt = 0; kt < nk; kt++) {
        const int stg = kt & 3;
        const int rem = nk - 1 - kt;   // chunks already issued beyond kt
        if (rem >= 2) { CP_WAIT2(); } else if (rem == 1) { CP_WAIT1(); } else { CP_WAIT0(); }
        __syncthreads();
        // issue chunk kt+3 into stage (kt-1)&3, whose readers are fenced above
        if (kt + 3 < nk) issue(kt + 3, (kt + 3) & 3);

        const uint32_t aS = sA + stg * STG_B + a_off;
        const uint32_t bS = sB + stg * STG_B + b_off;
        #pragma unroll
        for (int kk = 0; kk < 2; kk++) {
            unsigned af[4][4], bf[4][2];
            #pragma unroll
            for (int mt = 0; mt < 4; mt++)
                ldsm_x4(af[mt], aS + (mt * 16 * 40 + kk * 16) * 2);
            #pragma unroll
            for (int nt = 0; nt < 4; nt++)
                ldsm_x2(bf[nt], bS + (nt * 8 * 40 + kk * 16) * 2);
            #pragma unroll
            for (int mt = 0; mt < 4; mt++)
                #pragma unroll
                for (int nt = 0; nt < 4; nt++)
                    mma_f16(c[mt][nt], af[mt], bf[nt]);
        }
    }

    // ---------------- epilogue ----------------
    #pragma unroll
    for (int mt = 0; mt < 4; mt++) {
        #pragma unroll
        for (int nt = 0; nt < 4; nt++) {
            int r0 = m0 + wm * 64 + mt * 16 + gid;
            int r1 = r0 + 8;
            int cb = n0 + wn * 32 + nt * 8 + 2 * tig;
            float bs0 = bias[cb], bs1 = bias[cb + 1];
            float v00 = c[mt][nt][0] + bs0, v01 = c[mt][nt][1] + bs1;
            float v10 = c[mt][nt][2] + bs0, v11 = c[mt][nt][3] + bs1;

            if (EPI == 0) {
                if (cb < 256) { v00 *= SCALE; v01 *= SCALE; v10 *= SCALE; v11 *= SCALE; }
                *(__half2*)&Ch[(size_t)r0 * Nn + cb] = __floats2half2_rn(v00, v01);
                *(__half2*)&Ch[(size_t)r1 * Nn + cb] = __floats2half2_rn(v10, v11);
            } else if (EPI == 1) {
                const float kk = 0.70710678118654752f;
                v00 = 0.5f * v00 * (1.f + erff(v00 * kk));
                v01 = 0.5f * v01 * (1.f + erff(v01 * kk));
                v10 = 0.5f * v10 * (1.f + erff(v10 * kk));
                v11 = 0.5f * v11 * (1.f + erff(v11 * kk));
                *(__half2*)&Ch[(size_t)r0 * Nn + cb] = __floats2half2_rn(v00, v01);
                *(__half2*)&Ch[(size_t)r1 * Nn + cb] = __floats2half2_rn(v10, v11);
            } else if (EPI == 2) {
                #pragma unroll
                for (int rr = 0; rr < 2; rr++) {
                    int m = rr ? r1 : r0;
                    float va = rr ? v10 : v00, vb = rr ? v11 : v01;
                    int bw = m / NTOK, t = m % NTOK;
                    int b = bw >> 6, w = bw & 63;
                    int wh = w >> 3, ww = w & 7;
                    int r = t / 7, cc = t % 7;
                    int gh = wh * 7 + r + SHIFT; if (gh >= HW) gh -= HW;
                    int gw = ww * 7 + cc + SHIFT; if (gw >= HW) gw -= HW;
                    size_t dst = (size_t)(b * (HW*HW) + gh * HW + gw) * DIM + cb;
                    float2 rv = *(const float2*)&res[dst];
                    *(float2*)&Cf[dst] = make_float2(va + rv.x, vb + rv.y);
                }
            } else {
                size_t d0 = (size_t)r0 * Nn + cb, d1 = (size_t)r1 * Nn + cb;
                float2 ra = *(const float2*)&res[d0];
                float2 rb2 = *(const float2*)&res[d1];
                *(float2*)&Cf[d0] = make_float2(v00 + ra.x, v01 + ra.y);
                *(float2*)&Cf[d1] = make_float2(v10 + rb2.x, v11 + rb2.y);
            }
        }
    }
}

// ---------------- tensor-core attention (sP overlaid on sS) ----------------
__global__ void __launch_bounds__(256) attn_kernel(
    const __half* __restrict__ qkv, const float* __restrict__ bias,
    __half* __restrict__ out)
{
    __shared__ __half sQ [64][40];
    __shared__ __half sK [56][40];
    __shared__ __half sVT[32][72];
    __shared__ float  sS [64][60];   // scores; fp16 P overlaid row-for-row
    __shared__ int    regn[NTOK];

    // sP row n occupies the first 128 bytes of sS row n (stride 120 halves = 240 B)
    __half (*sP)[120] = reinterpret_cast<__half(*)[120]>(sS);

    const int bw = blockIdx.x >> 3;
    const int h  = blockIdx.x & 7;
    const int tid = threadIdx.x, lane = tid & 31, wid = tid >> 5;
    const int gid = lane >> 2, tig = lane & 3;

    // zero VT (k-padding cols 49..63 must be exact zeros; P pad handled in softmax)
    for (int i = tid; i < 32 * 36; i += 256) ((uint32_t*)sVT)[i] = 0;

    if (tid < NTOK) {
        int w = bw & 63;
        int wh = w >> 3, ww = w & 7;
        int r = tid / 7, c = tid % 7;
        int gh = wh * 7 + r, gw = ww * 7 + c;
        int rh = (gh < HW - WS) ? 0 : ((gh < HW - SHIFT) ? 1 : 2);
        int rw = (gw < HW - WS) ? 0 : ((gw < HW - SHIFT) ? 1 : 2);
        regn[tid] = rh * 3 + rw;
    }
    for (int i = tid; i < NTOK * 4; i += 256) {
        int n = i >> 2, d8 = (i & 3) * 8;
        size_t basep = (size_t)(bw * NTOK + n) * 768 + h * HD + d8;
        uint4 qu = *(const uint4*)&qkv[basep];
        uint4 ku = *(const uint4*)&qkv[basep + 256];
        uint4 vu = *(const uint4*)&qkv[basep + 512];
        *(uint4*)&sQ[n][d8] = qu;
        *(uint4*)&sK[n][d8] = ku;
        const __half* vh = (const __half*)&vu;
        #pragma unroll
        for (int j = 0; j < 8; j++) sVT[d8 + j][n] = vh[j];
    }
    __syncthreads();

    // ---- QK^T ----
    for (int t = wid; t < 28; t += 8) {
        int mt = t & 3, nt = t >> 2;
        int rb = mt * 16, nb = nt * 8;
        float c[4] = {0.f, 0.f, 0.f, 0.f};
        const uint32_t* qr0 = (const uint32_t*)&sQ[rb + gid][0];
        const uint32_t* qr1 = (const uint32_t*)&sQ[rb + gid + 8][0];
        const uint32_t* kr  = (const uint32_t*)&sK[nb + gid][0];
        #pragma unroll
        for (int ks = 0; ks < 2; ks++) {
            unsigned a[4] = { qr0[8*ks + tig], qr1[8*ks + tig],
                              qr0[8*ks + tig + 4], qr1[8*ks + tig + 4] };
            unsigned b[2] = { kr[8*ks + tig], kr[8*ks + tig + 4] };
            mma_f16(c, a, b);
        }
        sS[rb + gid    ][nb + 2*tig]     = c[0];
        sS[rb + gid    ][nb + 2*tig + 1] = c[1];
        sS[rb + gid + 8][nb + 2*tig]     = c[2];
        sS[rb + gid + 8][nb + 2*tig + 1] = c[3];
    }
    __syncthreads();

    // ---- softmax (warp per row); writes fp16 P over the same row ----
    const float* brow = bias + h * (NTOK * NTOK);
    bool has1 = lane < (NTOK - 32);
    int m1c = has1 ? lane + 32 : lane;

    for (int n = wid; n < NTOK; n += 8) {
        int rn = regn[n];
        float a0 = sS[n][lane] + brow[n * NTOK + lane]
                 + ((rn != regn[lane]) ? -100.f : 0.f);
        float a1 = has1 ? (sS[n][m1c] + brow[n * NTOK + m1c]
                 + ((rn != regn[m1c]) ? -100.f : 0.f)) : -1e30f;

        float mx = fmaxf(a0, a1);
        #pragma unroll
        for (int o = 16; o > 0; o >>= 1) mx = fmaxf(mx, __shfl_xor_sync(0xFFFFFFFFu, mx, o));
        float e0 = __expf(a0 - mx);
        float e1 = has1 ? __expf(a1 - mx) : 0.f;
        float sm = e0 + e1;
        #pragma unroll
        for (int o = 16; o > 0; o >>= 1) sm += __shfl_xor_sync(0xFFFFFFFFu, sm, o);
        float inv = 1.f / sm;
        __syncwarp();   // all aliased reads of row n complete before writes
        sP[n][lane]      = __float2half(e0 * inv);
        sP[n][lane + 32] = has1 ? __float2half(e1 * inv) : __half(0.f);  // cols 49..63 = 0
    }
    __syncthreads();

    // ---- PV ----
    for (int t = wid; t < 16; t += 8) {
        int mt = t & 3, nt = t >> 2;
        int rb = mt * 16, nb = nt * 8;
        float c[4] = {0.f, 0.f, 0.f, 0.f};
        const uint32_t* pr0 = (const uint32_t*)&sP[rb + gid][0];
        const uint32_t* pr1 = (const uint32_t*)&sP[rb + gid + 8][0];
        const uint32_t* vr  = (const uint32_t*)&sVT[nb + gid][0];
        #pragma unroll
        for (int ks = 0; ks < 4; ks++) {
            unsigned a[4] = { pr0[8*ks + tig], pr1[8*ks + tig],
                              pr0[8*ks + tig + 4], pr1[8*ks + tig + 4] };
            unsigned b[2] = { vr[8*ks + tig], vr[8*ks + tig + 4] };
            mma_f16(c, a, b);
        }
        int n0 = rb + gid, n1 = n0 + 8;
        int d = nb + 2 * tig;
        if (n0 < NTOK)
            *(__half2*)&out[(size_t)(bw * NTOK + n0) * 256 + h * HD + d] =
                __floats2half2_rn(c[0], c[1]);
        if (n1 < NTOK)
            *(__half2*)&out[(size_t)(bw * NTOK + n1) * 256 + h * HD + d] =
                __floats2half2_rn(c[2], c[3]);
    }
}

// ---------------- launcher ----------------
extern "C" void kernel_launch(void* const* d_in, const int* in_sizes, int n_in,
                              void* d_out, int out_size)
{
    (void)in_sizes; (void)n_in; (void)out_size;
    const float* x        = (const float*)d_in[0];
    const float* norm1_g  = (const float*)d_in[1];
    const float* norm1_b  = (const float*)d_in[2];
    const float* qkv_w    = (const float*)d_in[3];
    const float* qkv_b    = (const float*)d_in[4];
    const float* rel_tab  = (const float*)d_in[5];
    const float* proj_w   = (const float*)d_in[6];
    const float* proj_b   = (const float*)d_in[7];
    const float* norm2_g  = (const float*)d_in[8];
    const float* norm2_b  = (const float*)d_in[9];
    const float* fc1_w    = (const float*)d_in[10];
    const float* fc1_b    = (const float*)d_in[11];
    const float* fc2_w    = (const float*)d_in[12];
    const float* fc2_b    = (const float*)d_in[13];
    float* out = (float*)d_out;

    __half *p_a, *p_qkv, *p_h1, *p_wqkv, *p_wproj, *p_wfc1, *p_wfc2;
    float *p_xres, *p_bias;
    cudaGetSymbolAddress((void**)&p_a,     hb_a);
    cudaGetSymbolAddress((void**)&p_qkv,   hb_qkv);
    cudaGetSymbolAddress((void**)&p_h1,    hb_h1);
    cudaGetSymbolAddress((void**)&p_xres,  g_xres);
    cudaGetSymbolAddress((void**)&p_bias,  g_bias);
    cudaGetSymbolAddress((void**)&p_wqkv,  hw_qkv);
    cudaGetSymbolAddress((void**)&p_wproj, hw_proj);
    cudaGetSymbolAddress((void**)&p_wfc1,  hw_fc1);
    cudaGetSymbolAddress((void**)&p_wfc2,  hw_fc2);

    cudaFuncSetAttribute(hgemm<0>, cudaFuncAttributeMaxDynamicSharedMemorySize, GSMEM);
    cudaFuncSetAttribute(hgemm<1>, cudaFuncAttributeMaxDynamicSharedMemorySize, GSMEM);
    cudaFuncSetAttribute(hgemm<2>, cudaFuncAttributeMaxDynamicSharedMemorySize, GSMEM);
    cudaFuncSetAttribute(hgemm<3>, cudaFuncAttributeMaxDynamicSharedMemorySize, GSMEM);

    const int M = MTOK;

    wconv_kernel<<<(768*256 + 256*256 + 255)/256, 256>>>(qkv_w, p_wqkv, 768*256,
                                                         proj_w, p_wproj, 256*256);
    wconv_kernel<<<(1024*256 + 256*1024 + 255)/256, 256>>>(fc1_w, p_wfc1, 1024*256,
                                                           fc2_w, p_wfc2, 256*1024);
    bias_kernel<<<(NH*NTOK*NTOK + 255)/256, 256>>>(rel_tab, p_bias);
    ln_kernel<1><<<M/8, 256>>>(x, p_a, norm1_g, norm1_b);
    // slot #5 (profiled): qkv gemm
    hgemm<0><<<dim3(768/128, M/128), 256, GSMEM>>>(p_a, p_wqkv, qkv_b, nullptr, p_qkv, nullptr, M, 768, 256);
    attn_kernel<<<BW * NH, 256>>>(p_qkv, p_bias, p_a);
    hgemm<2><<<dim3(256/128, M/128), 256, GSMEM>>>(p_a, p_wproj, proj_b, p_xres, nullptr, x, M, 256, 256);
    ln_kernel<0><<<M/8, 256>>>(p_xres, p_a, norm2_g, norm2_b);
    hgemm<1><<<dim3(1024/128, M/128), 256, GSMEM>>>(p_a, p_wfc1, fc1_b, nullptr, p_h1, nullptr, M, 1024, 256);
    hgemm<3><<<dim3(256/128, M/128), 256, GSMEM>>>(p_h1, p_wfc2, fc2_b, out, nullptr, p_xres, M, 256, 1024);
}

// round 10
// speedup vs baseline: 1.0519x; 1.0519x over previous
#include <cuda_runtime.h>
#include <cuda_fp16.h>
#include <math.h>
#include <stdint.h>

// ---------------- problem constants ----------------
#define BATCH   32
#define HW      56
#define DIM     256
#define WS      7
#define SHIFT   3
#define NH      8
#define HD      32
#define NTOK    49
#define NWIN    64
#define BW      (BATCH*NWIN)
#define MTOK    (BATCH*HW*HW)   // 100352
#define SCALE   0.17677669529663687f

// ---------------- scratch ----------------
__device__ __half hb_a  [(size_t)MTOK * 256];
__device__ __half hb_qkv[(size_t)MTOK * 768];
__device__ __half hb_h1 [(size_t)MTOK * 1024];
__device__ float  g_xres[(size_t)MTOK * 256];
__device__ __half g_biasM[4 * NH * NTOK * NTOK];   // masked bias, 4 window types
__device__ __half hw_qkv [768 * 256];
__device__ __half hw_proj[256 * 256];
__device__ __half hw_fc1 [1024 * 256];
__device__ __half hw_fc2 [256 * 1024];

// ---------------- PTX helpers ----------------
__device__ __forceinline__ uint32_t cvta_s(const void* p) {
    uint32_t a;
    asm("{ .reg .u64 t; cvta.to.shared.u64 t, %1; cvt.u32.u64 %0, t; }" : "=r"(a) : "l"(p));
    return a;
}
__device__ __forceinline__ void ldsm_x4(unsigned* r, uint32_t a) {
    asm volatile("ldmatrix.sync.aligned.m8n8.x4.shared.b16 {%0,%1,%2,%3}, [%4];"
        : "=r"(r[0]), "=r"(r[1]), "=r"(r[2]), "=r"(r[3]) : "r"(a));
}
#define CP_ASYNC16(dst, src) asm volatile("cp.async.ca.shared.global [%0], [%1], 16;" :: "r"(dst), "l"(src))
#define CP_COMMIT()          asm volatile("cp.async.commit_group;" ::: "memory")
#define CP_WAIT1()           asm volatile("cp.async.wait_group 1;" ::: "memory")
#define CP_WAIT0()           asm volatile("cp.async.wait_group 0;" ::: "memory")

__device__ __forceinline__ void mma_f16(float* c, const unsigned* a, const unsigned* b) {
    asm("mma.sync.aligned.m16n8k16.row.col.f32.f16.f16.f32 "
        "{%0,%1,%2,%3},{%4,%5,%6,%7},{%8,%9},{%0,%1,%2,%3};"
        : "+f"(c[0]), "+f"(c[1]), "+f"(c[2]), "+f"(c[3])
        : "r"(a[0]), "r"(a[1]), "r"(a[2]), "r"(a[3]), "r"(b[0]), "r"(b[1]));
}

// ---------------- weight fp32 -> fp16 ----------------
__global__ void wconv_kernel(const float* __restrict__ w0, __half* __restrict__ o0, int n0,
                             const float* __restrict__ w1, __half* __restrict__ o1, int n1)
{
    int i = blockIdx.x * 256 + threadIdx.x;
    if (i < n0) o0[i] = __float2half(w0[i]);
    else if (i < n0 + n1) o1[i - n0] = __float2half(w1[i - n0]);
}

// ---------------- masked rel-pos bias table: [type][head][n][m] fp16 -------
// type = (wh==7)*2 + (ww==7): region id varies inside a window only on the
// last window row/col (gh in [49,53) -> 1, [53,56) -> 2; else 0).
__global__ void biasm_kernel(const float* __restrict__ rel_table, __half* __restrict__ bm)
{
    int i = blockIdx.x * 256 + threadIdx.x;
    if (i >= 4 * NH * NTOK * NTOK) return;
    int type = i / (NH * NTOK * NTOK);
    int rem  = i % (NH * NTOK * NTOK);
    int h = rem / (NTOK * NTOK);
    int s = rem % (NTOK * NTOK);
    int n = s / NTOK, m = s % NTOK;
    int rn = n / 7, cn = n % 7, rm = m / 7, cm = m % 7;
    int idx = (rn - rm + 6) * 13 + (cn - cm + 6);
    float v = rel_table[idx * NH + h];
    int th = type >> 1, tw = type & 1;
    int rhn = th ? (rn < 4 ? 1 : 2) : 0;
    int rwn = tw ? (cn < 4 ? 1 : 2) : 0;
    int rhm = th ? (rm < 4 ? 1 : 2) : 0;
    int rwm = tw ? (cm < 4 ? 1 : 2) : 0;
    if (rhn * 3 + rwn != rhm * 3 + rwm) v -= 100.f;
    bm[i] = __float2half(v);
}

// ---------------- LayerNorm: one row per warp, float4 I/O ----------------
template<int PERM>
__global__ void __launch_bounds__(256) ln_kernel(
    const float* __restrict__ in, __half* __restrict__ out,
    const float* __restrict__ gam, const float* __restrict__ bet)
{
    const int row = blockIdx.x * 8 + (threadIdx.x >> 5);
    const int lane = threadIdx.x & 31;
    int src;
    if (PERM) {
        int bw = row / NTOK, t = row % NTOK;
        int b = bw >> 6, w = bw & 63;
        int wh = w >> 3, ww = w & 7;
        int r = t / 7, c = t % 7;
        int gh = wh * 7 + r + SHIFT; if (gh >= HW) gh -= HW;
        int gw = ww * 7 + c + SHIFT; if (gw >= HW) gw -= HW;
        src = (b * (HW*HW) + gh * HW + gw) * DIM;
    } else {
        src = row * DIM;
    }
    const int col = lane * 8;
    float4 v0 = *(const float4*)&in[src + col];
    float4 v1 = *(const float4*)&in[src + col + 4];

    float s = v0.x+v0.y+v0.z+v0.w + v1.x+v1.y+v1.z+v1.w;
    float q = v0.x*v0.x+v0.y*v0.y+v0.z*v0.z+v0.w*v0.w
            + v1.x*v1.x+v1.y*v1.y+v1.z*v1.z+v1.w*v1.w;
    #pragma unroll
    for (int o = 16; o > 0; o >>= 1) {
        s += __shfl_xor_sync(0xFFFFFFFFu, s, o);
        q += __shfl_xor_sync(0xFFFFFFFFu, q, o);
    }
    float mu = s * (1.0f/DIM);
    float rstd = rsqrtf(q * (1.0f/DIM) - mu*mu + 1e-5f);

    float4 g0 = *(const float4*)&gam[col], g1 = *(const float4*)&gam[col+4];
    float4 b0 = *(const float4*)&bet[col], b1 = *(const float4*)&bet[col+4];

    uint4 o8;
    ((__half2*)&o8)[0] = __floats2half2_rn((v0.x-mu)*rstd*g0.x+b0.x, (v0.y-mu)*rstd*g0.y+b0.y);
    ((__half2*)&o8)[1] = __floats2half2_rn((v0.z-mu)*rstd*g0.z+b0.z, (v0.w-mu)*rstd*g0.w+b0.w);
    ((__half2*)&o8)[2] = __floats2half2_rn((v1.x-mu)*rstd*g1.x+b1.x, (v1.y-mu)*rstd*g1.y+b1.y);
    ((__half2*)&o8)[3] = __floats2half2_rn((v1.z-mu)*rstd*g1.z+b1.z, (v1.w-mu)*rstd*g1.w+b1.w);
    *(uint4*)&out[(size_t)row * DIM + col] = o8;
}

// ---------------- fp16 GEMM: cp.async 3-stage + ldmatrix, 1 sync/chunk ----
#define STG_H    (128 * 40)
#define STG_B    (STG_H * 2)
#define GSMEM    (6 * STG_B)   // 61440 B

template<int EPI>
__global__ void __launch_bounds__(256, 2) hgemm(
    const __half* __restrict__ A, const __half* __restrict__ B,
    const float* __restrict__ bias, float* __restrict__ Cf, __half* __restrict__ Ch,
    const float* __restrict__ res, int M, int Nn, int K)
{
    extern __shared__ __half dsm[];

    const int tid = threadIdx.x;
    const int lane = tid & 31, wid = tid >> 5;
    const int wm = wid >> 2, wn = wid & 3;
    const int gid = lane >> 2, tig = lane & 3;
    const int m0 = blockIdx.y * 128, n0 = blockIdx.x * 128;

    const uint32_t sbase = cvta_s(dsm);
    const uint32_t sA = sbase;
    const uint32_t sB = sbase + 3 * STG_B;

    const int lr0 = tid >> 2, lq0 = (tid & 3);
    const int lr1 = lr0 + 64;

    float c[4][4][4];
    #pragma unroll
    for (int i = 0; i < 4; i++)
        #pragma unroll
        for (int j = 0; j < 4; j++)
            #pragma unroll
            for (int r = 0; r < 4; r++) c[i][j][r] = 0.f;

    const int nk = K >> 5;

    // A ldmatrix: row = wm*64 + mt*16 + (lane&15), col = kk*16 + (lane>>4)*8
    const uint32_t a_off = ((uint32_t)(wm * 64 + (lane & 15)) * 40 + (lane >> 4) * 8) * 2;
    // B ldmatrix x4 over nt-pair: row = wn*32 + p*16 + ((lane>>4)&1)*8 + (lane&7),
    //                             col = kk*16 + ((lane>>3)&1)*8
    const uint32_t b_off = ((uint32_t)(wn * 32 + ((lane >> 4) & 1) * 8 + (lane & 7)) * 40
                           + ((lane >> 3) & 1) * 8) * 2;

    auto issue = [&](int kt, int stg) {
        const size_t kb = (size_t)kt * 32 + lq0 * 8;
        uint32_t dA0 = sA + stg * STG_B + (lr0 * 40 + lq0 * 8) * 2;
        uint32_t dA1 = sA + stg * STG_B + (lr1 * 40 + lq0 * 8) * 2;
        uint32_t dB0 = sB + stg * STG_B + (lr0 * 40 + lq0 * 8) * 2;
        uint32_t dB1 = sB + stg * STG_B + (lr1 * 40 + lq0 * 8) * 2;
        CP_ASYNC16(dA0, &A[(size_t)(m0 + lr0) * K + kb]);
        CP_ASYNC16(dA1, &A[(size_t)(m0 + lr1) * K + kb]);
        CP_ASYNC16(dB0, &B[(size_t)(n0 + lr0) * K + kb]);
        CP_ASYNC16(dB1, &B[(size_t)(n0 + lr1) * K + kb]);
        CP_COMMIT();
    };

    issue(0, 0);
    issue(1, 1);

    for (int kt = 0; kt < nk; kt++) {
        const int stg = kt % 3;
        if (kt + 2 < nk) { CP_WAIT1(); } else { CP_WAIT0(); }
        __syncthreads();
        if (kt + 2 < nk) issue(kt + 2, (kt + 2) % 3);

        const uint32_t aS = sA + stg * STG_B + a_off;
        const uint32_t bS = sB + stg * STG_B + b_off;
        #pragma unroll
        for (int kk = 0; kk < 2; kk++) {
            unsigned af[4][4], bf[4][2];
            #pragma unroll
            for (int mt = 0; mt < 4; mt++)
                ldsm_x4(af[mt], aS + (mt * 16 * 40 + kk * 16) * 2);
            #pragma unroll
            for (int p = 0; p < 2; p++) {
                unsigned br[4];
                ldsm_x4(br, bS + (p * 16 * 40 + kk * 16) * 2);
                bf[2*p][0]   = br[0]; bf[2*p][1]   = br[1];
                bf[2*p+1][0] = br[2]; bf[2*p+1][1] = br[3];
            }
            #pragma unroll
            for (int mt = 0; mt < 4; mt++)
                #pragma unroll
                for (int nt = 0; nt < 4; nt++)
                    mma_f16(c[mt][nt], af[mt], bf[nt]);
        }
    }

    // ---------------- epilogue ----------------
    #pragma unroll
    for (int mt = 0; mt < 4; mt++) {
        #pragma unroll
        for (int nt = 0; nt < 4; nt++) {
            int r0 = m0 + wm * 64 + mt * 16 + gid;
            int r1 = r0 + 8;
            int cb = n0 + wn * 32 + nt * 8 + 2 * tig;
            float bs0 = bias[cb], bs1 = bias[cb + 1];
            float v00 = c[mt][nt][0] + bs0, v01 = c[mt][nt][1] + bs1;
            float v10 = c[mt][nt][2] + bs0, v11 = c[mt][nt][3] + bs1;

            if (EPI == 0) {
                if (cb < 256) { v00 *= SCALE; v01 *= SCALE; v10 *= SCALE; v11 *= SCALE; }
                *(__half2*)&Ch[(size_t)r0 * Nn + cb] = __floats2half2_rn(v00, v01);
                *(__half2*)&Ch[(size_t)r1 * Nn + cb] = __floats2half2_rn(v10, v11);
            } else if (EPI == 1) {
                const float kk = 0.70710678118654752f;
                v00 = 0.5f * v00 * (1.f + erff(v00 * kk));
                v01 = 0.5f * v01 * (1.f + erff(v01 * kk));
                v10 = 0.5f * v10 * (1.f + erff(v10 * kk));
                v11 = 0.5f * v11 * (1.f + erff(v11 * kk));
                *(__half2*)&Ch[(size_t)r0 * Nn + cb] = __floats2half2_rn(v00, v01);
                *(__half2*)&Ch[(size_t)r1 * Nn + cb] = __floats2half2_rn(v10, v11);
            } else if (EPI == 2) {
                #pragma unroll
                for (int rr = 0; rr < 2; rr++) {
                    int m = rr ? r1 : r0;
                    float va = rr ? v10 : v00, vb = rr ? v11 : v01;
                    int bw = m / NTOK, t = m % NTOK;
                    int b = bw >> 6, w = bw & 63;
                    int wh = w >> 3, ww = w & 7;
                    int r = t / 7, cc = t % 7;
                    int gh = wh * 7 + r + SHIFT; if (gh >= HW) gh -= HW;
                    int gw = ww * 7 + cc + SHIFT; if (gw >= HW) gw -= HW;
                    size_t dst = (size_t)(b * (HW*HW) + gh * HW + gw) * DIM + cb;
                    float2 rv = *(const float2*)&res[dst];
                    *(float2*)&Cf[dst] = make_float2(va + rv.x, vb + rv.y);
                }
            } else {
                size_t d0 = (size_t)r0 * Nn + cb, d1 = (size_t)r1 * Nn + cb;
                float2 ra = *(const float2*)&res[d0];
                float2 rb2 = *(const float2*)&res[d1];
                *(float2*)&Cf[d0] = make_float2(v00 + ra.x, v01 + ra.y);
                *(float2*)&Cf[d1] = make_float2(v10 + rb2.x, v11 + rb2.y);
            }
        }
    }
}

// ---------------- tensor-core attention (masked-bias table, sP overlay) ----
__global__ void __launch_bounds__(256) attn_kernel(
    const __half* __restrict__ qkv, const __half* __restrict__ biasM,
    __half* __restrict__ out)
{
    __shared__ __half sQ [64][40];
    __shared__ __half sK [56][40];
    __shared__ __half sVT[32][72];
    __shared__ float  sS [64][60];   // scores; fp16 P overlaid row-for-row

    __half (*sP)[120] = reinterpret_cast<__half(*)[120]>(sS);

    const int bw = blockIdx.x >> 3;
    const int h  = blockIdx.x & 7;
    const int tid = threadIdx.x, lane = tid & 31, wid = tid >> 5;
    const int gid = lane >> 2, tig = lane & 3;

    // window type: region id varies only in the last window row/col
    const int w = bw & 63;
    const int type = (((w >> 3) == 7) ? 2 : 0) + (((w & 7) == 7) ? 1 : 0);
    const __half* bm = biasM + ((size_t)(type * NH + h)) * (NTOK * NTOK);

    for (int i = tid; i < 32 * 36; i += 256) ((uint32_t*)sVT)[i] = 0;

    for (int i = tid; i < NTOK * 4; i += 256) {
        int n = i >> 2, d8 = (i & 3) * 8;
        size_t basep = (size_t)(bw * NTOK + n) * 768 + h * HD + d8;
        uint4 qu = *(const uint4*)&qkv[basep];
        uint4 ku = *(const uint4*)&qkv[basep + 256];
        uint4 vu = *(const uint4*)&qkv[basep + 512];
        *(uint4*)&sQ[n][d8] = qu;
        *(uint4*)&sK[n][d8] = ku;
        const __half* vh = (const __half*)&vu;
        #pragma unroll
        for (int j = 0; j < 8; j++) sVT[d8 + j][n] = vh[j];
    }
    __syncthreads();

    // ---- QK^T ----
    for (int t = wid; t < 28; t += 8) {
        int mt = t & 3, nt = t >> 2;
        int rb = mt * 16, nb = nt * 8;
        float c[4] = {0.f, 0.f, 0.f, 0.f};
        const uint32_t* qr0 = (const uint32_t*)&sQ[rb + gid][0];
        const uint32_t* qr1 = (const uint32_t*)&sQ[rb + gid + 8][0];
        const uint32_t* kr  = (const uint32_t*)&sK[nb + gid][0];
        #pragma unroll
        for (int ks = 0; ks < 2; ks++) {
            unsigned a[4] = { qr0[8*ks + tig], qr1[8*ks + tig],
                              qr0[8*ks + tig + 4], qr1[8*ks + tig + 4] };
            unsigned b[2] = { kr[8*ks + tig], kr[8*ks + tig + 4] };
            mma_f16(c, a, b);
        }
        sS[rb + gid    ][nb + 2*tig]     = c[0];
        sS[rb + gid    ][nb + 2*tig + 1] = c[1];
        sS[rb + gid + 8][nb + 2*tig]     = c[2];
        sS[rb + gid + 8][nb + 2*tig + 1] = c[3];
    }
    __syncthreads();

    // ---- softmax (warp per row); masked bias from table ----
    bool has1 = lane < (NTOK - 32);
    int m1c = has1 ? lane + 32 : lane;

    for (int n = wid; n < NTOK; n += 8) {
        float a0 = sS[n][lane] + __half2float(bm[n * NTOK + lane]);
        float a1 = has1 ? (sS[n][m1c] + __half2float(bm[n * NTOK + m1c])) : -1e30f;

        float mx = fmaxf(a0, a1);
        #pragma unroll
        for (int o = 16; o > 0; o >>= 1) mx = fmaxf(mx, __shfl_xor_sync(0xFFFFFFFFu, mx, o));
        float e0 = __expf(a0 - mx);
        float e1 = has1 ? __expf(a1 - mx) : 0.f;
        float sm = e0 + e1;
        #pragma unroll
        for (int o = 16; o > 0; o >>= 1) sm += __shfl_xor_sync(0xFFFFFFFFu, sm, o);
        float inv = 1.f / sm;
        __syncwarp();
        sP[n][lane]      = __float2half(e0 * inv);
        sP[n][lane + 32] = has1 ? __float2half(e1 * inv) : __half(0.f);
    }
    __syncthreads();

    // ---- PV ----
    for (int t = wid; t < 16; t += 8) {
        int mt = t & 3, nt = t >> 2;
        int rb = mt * 16, nb = nt * 8;
        float c[4] = {0.f, 0.f, 0.f, 0.f};
        const uint32_t* pr0 = (const uint32_t*)&sP[rb + gid][0];
        const uint32_t* pr1 = (const uint32_t*)&sP[rb + gid + 8][0];
        const uint32_t* vr  = (const uint32_t*)&sVT[nb + gid][0];
        #pragma unroll
        for (int ks = 0; ks < 4; ks++) {
            unsigned a[4] = { pr0[8*ks + tig], pr1[8*ks + tig],
                              pr0[8*ks + tig + 4], pr1[8*ks + tig + 4] };
            unsigned b[2] = { vr[8*ks + tig], vr[8*ks + tig + 4] };
            mma_f16(c, a, b);
        }
        int n0 = rb + gid, n1 = n0 + 8;
        int d = nb + 2 * tig;
        if (n0 < NTOK)
            *(__half2*)&out[(size_t)(bw * NTOK + n0) * 256 + h * HD + d] =
                __floats2half2_rn(c[0], c[1]);
        if (n1 < NTOK)
            *(__half2*)&out[(size_t)(bw * NTOK + n1) * 256 + h * HD + d] =
                __floats2half2_rn(c[2], c[3]);
    }
}

// ---------------- launcher ----------------
extern "C" void kernel_launch(void* const* d_in, const int* in_sizes, int n_in,
                              void* d_out, int out_size)
{
    (void)in_sizes; (void)n_in; (void)out_size;
    const float* x        = (const float*)d_in[0];
    const float* norm1_g  = (const float*)d_in[1];
    const float* norm1_b  = (const float*)d_in[2];
    const float* qkv_w    = (const float*)d_in[3];
    const float* qkv_b    = (const float*)d_in[4];
    const float* rel_tab  = (const float*)d_in[5];
    const float* proj_w   = (const float*)d_in[6];
    const float* proj_b   = (const float*)d_in[7];
    const float* norm2_g  = (const float*)d_in[8];
    const float* norm2_b  = (const float*)d_in[9];
    const float* fc1_w    = (const float*)d_in[10];
    const float* fc1_b    = (const float*)d_in[11];
    const float* fc2_w    = (const float*)d_in[12];
    const float* fc2_b    = (const float*)d_in[13];
    float* out = (float*)d_out;

    __half *p_a, *p_qkv, *p_h1, *p_wqkv, *p_wproj, *p_wfc1, *p_wfc2, *p_biasM;
    float *p_xres;
    cudaGetSymbolAddress((void**)&p_a,     hb_a);
    cudaGetSymbolAddress((void**)&p_qkv,   hb_qkv);
    cudaGetSymbolAddress((void**)&p_h1,    hb_h1);
    cudaGetSymbolAddress((void**)&p_xres,  g_xres);
    cudaGetSymbolAddress((void**)&p_biasM, g_biasM);
    cudaGetSymbolAddress((void**)&p_wqkv,  hw_qkv);
    cudaGetSymbolAddress((void**)&p_wproj, hw_proj);
    cudaGetSymbolAddress((void**)&p_wfc1,  hw_fc1);
    cudaGetSymbolAddress((void**)&p_wfc2,  hw_fc2);

    cudaFuncSetAttribute(hgemm<0>, cudaFuncAttributeMaxDynamicSharedMemorySize, GSMEM);
    cudaFuncSetAttribute(hgemm<1>, cudaFuncAttributeMaxDynamicSharedMemorySize, GSMEM);
    cudaFuncSetAttribute(hgemm<2>, cudaFuncAttributeMaxDynamicSharedMemorySize, GSMEM);
    cudaFuncSetAttribute(hgemm<3>, cudaFuncAttributeMaxDynamicSharedMemorySize, GSMEM);

    const int M = MTOK;

    wconv_kernel<<<(768*256 + 256*256 + 255)/256, 256>>>(qkv_w, p_wqkv, 768*256,
                                                         proj_w, p_wproj, 256*256);
    wconv_kernel<<<(1024*256 + 256*1024 + 255)/256, 256>>>(fc1_w, p_wfc1, 1024*256,
                                                           fc2_w, p_wfc2, 256*1024);
    biasm_kernel<<<(4*NH*NTOK*NTOK + 255)/256, 256>>>(rel_tab, p_biasM);
    ln_kernel<1><<<M/8, 256>>>(x, p_a, norm1_g, norm1_b);
    // slot #5 (profiled): qkv gemm
    hgemm<0><<<dim3(768/128, M/128), 256, GSMEM>>>(p_a, p_wqkv, qkv_b, nullptr, p_qkv, nullptr, M, 768, 256);
    attn_kernel<<<BW * NH, 256>>>(p_qkv, p_biasM, p_a);
    hgemm<2><<<dim3(256/128, M/128), 256, GSMEM>>>(p_a, p_wproj, proj_b, p_xres, nullptr, x, M, 256, 256);
    ln_kernel<0><<<M/8, 256>>>(p_xres, p_a, norm2_g, norm2_b);
    hgemm<1><<<dim3(1024/128, M/128), 256, GSMEM>>>(p_a, p_wfc1, fc1_b, nullptr, p_h1, nullptr, M, 1024, 256);
    hgemm<3><<<dim3(256/128, M/128), 256, GSMEM>>>(p_h1, p_wfc2, fc2_b, out, nullptr, p_xres, M, 256, 1024);
}

// round 11
// speedup vs baseline: 1.0986x; 1.0444x over previous
#include <cuda_runtime.h>
#include <cuda_fp16.h>
#include <math.h>
#include <stdint.h>

// ---------------- problem constants ----------------
#define BATCH   32
#define HW      56
#define DIM     256
#define WS      7
#define SHIFT   3
#define NH      8
#define HD      32
#define NTOK    49
#define NWIN    64
#define BW      (BATCH*NWIN)
#define MTOK    (BATCH*HW*HW)   // 100352
#define SCALE   0.17677669529663687f

// ---------------- scratch ----------------
__device__ __half hb_a  [(size_t)MTOK * 256];
__device__ __half hb_qkv[(size_t)MTOK * 768];
__device__ __half hb_h1 [(size_t)MTOK * 1024];
__device__ float  g_xres[(size_t)MTOK * 256];
__device__ __half g_biasM[4 * NH * NTOK * NTOK];   // masked bias, 4 window types
__device__ __half hw_qkv [768 * 256];
__device__ __half hw_proj[256 * 256];
__device__ __half hw_fc1 [1024 * 256];
__device__ __half hw_fc2 [256 * 1024];

// ---------------- PTX helpers ----------------
__device__ __forceinline__ uint32_t cvta_s(const void* p) {
    uint32_t a;
    asm("{ .reg .u64 t; cvta.to.shared.u64 t, %1; cvt.u32.u64 %0, t; }" : "=r"(a) : "l"(p));
    return a;
}
__device__ __forceinline__ void ldsm_x4(unsigned* r, uint32_t a) {
    asm volatile("ldmatrix.sync.aligned.m8n8.x4.shared.b16 {%0,%1,%2,%3}, [%4];"
        : "=r"(r[0]), "=r"(r[1]), "=r"(r[2]), "=r"(r[3]) : "r"(a));
}
#define CP_ASYNC16(dst, src) asm volatile("cp.async.ca.shared.global [%0], [%1], 16;" :: "r"(dst), "l"(src))
#define CP_COMMIT()          asm volatile("cp.async.commit_group;" ::: "memory")
#define CP_WAIT1()           asm volatile("cp.async.wait_group 1;" ::: "memory")
#define CP_WAIT0()           asm volatile("cp.async.wait_group 0;" ::: "memory")

__device__ __forceinline__ void mma_f16(float* c, const unsigned* a, const unsigned* b) {
    asm("mma.sync.aligned.m16n8k16.row.col.f32.f16.f16.f32 "
        "{%0,%1,%2,%3},{%4,%5,%6,%7},{%8,%9},{%0,%1,%2,%3};"
        : "+f"(c[0]), "+f"(c[1]), "+f"(c[2]), "+f"(c[3])
        : "r"(a[0]), "r"(a[1]), "r"(a[2]), "r"(a[3]), "r"(b[0]), "r"(b[1]));
}

// ---------------- weight fp32 -> fp16 ----------------
__global__ void wconv_kernel(const float* __restrict__ w0, __half* __restrict__ o0, int n0,
                             const float* __restrict__ w1, __half* __restrict__ o1, int n1)
{
    int i = blockIdx.x * 256 + threadIdx.x;
    if (i < n0) o0[i] = __float2half(w0[i]);
    else if (i < n0 + n1) o1[i - n0] = __float2half(w1[i - n0]);
}

// ---------------- masked rel-pos bias table ----------------
__global__ void biasm_kernel(const float* __restrict__ rel_table, __half* __restrict__ bm)
{
    int i = blockIdx.x * 256 + threadIdx.x;
    if (i >= 4 * NH * NTOK * NTOK) return;
    int type = i / (NH * NTOK * NTOK);
    int rem  = i % (NH * NTOK * NTOK);
    int h = rem / (NTOK * NTOK);
    int s = rem % (NTOK * NTOK);
    int n = s / NTOK, m = s % NTOK;
    int rn = n / 7, cn = n % 7, rm = m / 7, cm = m % 7;
    int idx = (rn - rm + 6) * 13 + (cn - cm + 6);
    float v = rel_table[idx * NH + h];
    int th = type >> 1, tw = type & 1;
    int rhn = th ? (rn < 4 ? 1 : 2) : 0;
    int rwn = tw ? (cn < 4 ? 1 : 2) : 0;
    int rhm = th ? (rm < 4 ? 1 : 2) : 0;
    int rwm = tw ? (cm < 4 ? 1 : 2) : 0;
    if (rhn * 3 + rwn != rhm * 3 + rwm) v -= 100.f;
    bm[i] = __float2half(v);
}

// ---------------- LayerNorm: one row per warp, float4 I/O ----------------
template<int PERM>
__global__ void __launch_bounds__(256) ln_kernel(
    const float* __restrict__ in, __half* __restrict__ out,
    const float* __restrict__ gam, const float* __restrict__ bet)
{
    const int row = blockIdx.x * 8 + (threadIdx.x >> 5);
    const int lane = threadIdx.x & 31;
    int src;
    if (PERM) {
        int bw = row / NTOK, t = row % NTOK;
        int b = bw >> 6, w = bw & 63;
        int wh = w >> 3, ww = w & 7;
        int r = t / 7, c = t % 7;
        int gh = wh * 7 + r + SHIFT; if (gh >= HW) gh -= HW;
        int gw = ww * 7 + c + SHIFT; if (gw >= HW) gw -= HW;
        src = (b * (HW*HW) + gh * HW + gw) * DIM;
    } else {
        src = row * DIM;
    }
    const int col = lane * 8;
    float4 v0 = *(const float4*)&in[src + col];
    float4 v1 = *(const float4*)&in[src + col + 4];

    float s = v0.x+v0.y+v0.z+v0.w + v1.x+v1.y+v1.z+v1.w;
    float q = v0.x*v0.x+v0.y*v0.y+v0.z*v0.z+v0.w*v0.w
            + v1.x*v1.x+v1.y*v1.y+v1.z*v1.z+v1.w*v1.w;
    #pragma unroll
    for (int o = 16; o > 0; o >>= 1) {
        s += __shfl_xor_sync(0xFFFFFFFFu, s, o);
        q += __shfl_xor_sync(0xFFFFFFFFu, q, o);
    }
    float mu = s * (1.0f/DIM);
    float rstd = rsqrtf(q * (1.0f/DIM) - mu*mu + 1e-5f);

    float4 g0 = *(const float4*)&gam[col], g1 = *(const float4*)&gam[col+4];
    float4 b0 = *(const float4*)&bet[col], b1 = *(const float4*)&bet[col+4];

    uint4 o8;
    ((__half2*)&o8)[0] = __floats2half2_rn((v0.x-mu)*rstd*g0.x+b0.x, (v0.y-mu)*rstd*g0.y+b0.y);
    ((__half2*)&o8)[1] = __floats2half2_rn((v0.z-mu)*rstd*g0.z+b0.z, (v0.w-mu)*rstd*g0.w+b0.w);
    ((__half2*)&o8)[2] = __floats2half2_rn((v1.x-mu)*rstd*g1.x+b1.x, (v1.y-mu)*rstd*g1.y+b1.y);
    ((__half2*)&o8)[3] = __floats2half2_rn((v1.z-mu)*rstd*g1.z+b1.z, (v1.w-mu)*rstd*g1.w+b1.w);
    *(uint4*)&out[(size_t)row * DIM + col] = o8;
}

// ---------------- fp16 GEMM: cp.async 3-stage + ldmatrix ----------------
#define STG_H    (128 * 40)
#define STG_B    (STG_H * 2)
#define GSMEM    (6 * STG_B)   // 61440 B

template<int EPI>
__global__ void __launch_bounds__(256, 2) hgemm(
    const __half* __restrict__ A, const __half* __restrict__ B,
    const float* __restrict__ bias, float* __restrict__ Cf, __half* __restrict__ Ch,
    const float* __restrict__ res, int M, int Nn, int K)
{
    extern __shared__ __half dsm[];

    const int tid = threadIdx.x;
    const int lane = tid & 31, wid = tid >> 5;
    const int wm = wid >> 2, wn = wid & 3;
    const int gid = lane >> 2, tig = lane & 3;
    const int m0 = blockIdx.y * 128, n0 = blockIdx.x * 128;

    const uint32_t sbase = cvta_s(dsm);
    const uint32_t sA = sbase;
    const uint32_t sB = sbase + 3 * STG_B;

    const int lr0 = tid >> 2, lq0 = (tid & 3);
    const int lr1 = lr0 + 64;

    float c[4][4][4];
    #pragma unroll
    for (int i = 0; i < 4; i++)
        #pragma unroll
        for (int j = 0; j < 4; j++)
            #pragma unroll
            for (int r = 0; r < 4; r++) c[i][j][r] = 0.f;

    const int nk = K >> 5;

    const uint32_t a_off = ((uint32_t)(wm * 64 + (lane & 15)) * 40 + (lane >> 4) * 8) * 2;
    const uint32_t b_off = ((uint32_t)(wn * 32 + ((lane >> 4) & 1) * 8 + (lane & 7)) * 40
                           + ((lane >> 3) & 1) * 8) * 2;

    auto issue = [&](int kt, int stg) {
        const size_t kb = (size_t)kt * 32 + lq0 * 8;
        uint32_t dA0 = sA + stg * STG_B + (lr0 * 40 + lq0 * 8) * 2;
        uint32_t dA1 = sA + stg * STG_B + (lr1 * 40 + lq0 * 8) * 2;
        uint32_t dB0 = sB + stg * STG_B + (lr0 * 40 + lq0 * 8) * 2;
        uint32_t dB1 = sB + stg * STG_B + (lr1 * 40 + lq0 * 8) * 2;
        CP_ASYNC16(dA0, &A[(size_t)(m0 + lr0) * K + kb]);
        CP_ASYNC16(dA1, &A[(size_t)(m0 + lr1) * K + kb]);
        CP_ASYNC16(dB0, &B[(size_t)(n0 + lr0) * K + kb]);
        CP_ASYNC16(dB1, &B[(size_t)(n0 + lr1) * K + kb]);
        CP_COMMIT();
    };

    issue(0, 0);
    issue(1, 1);

    for (int kt = 0; kt < nk; kt++) {
        const int stg = kt % 3;
        if (kt + 2 < nk) { CP_WAIT1(); } else { CP_WAIT0(); }
        __syncthreads();
        if (kt + 2 < nk) issue(kt + 2, (kt + 2) % 3);

        const uint32_t aS = sA + stg * STG_B + a_off;
        const uint32_t bS = sB + stg * STG_B + b_off;
        #pragma unroll
        for (int kk = 0; kk < 2; kk++) {
            unsigned af[4][4], bf[4][2];
            #pragma unroll
            for (int mt = 0; mt < 4; mt++)
                ldsm_x4(af[mt], aS + (mt * 16 * 40 + kk * 16) * 2);
            #pragma unroll
            for (int p = 0; p < 2; p++) {
                unsigned br[4];
                ldsm_x4(br, bS + (p * 16 * 40 + kk * 16) * 2);
                bf[2*p][0]   = br[0]; bf[2*p][1]   = br[1];
                bf[2*p+1][0] = br[2]; bf[2*p+1][1] = br[3];
            }
            #pragma unroll
            for (int mt = 0; mt < 4; mt++)
                #pragma unroll
                for (int nt = 0; nt < 4; nt++)
                    mma_f16(c[mt][nt], af[mt], bf[nt]);
        }
    }

    // ---------------- epilogue ----------------
    if (EPI == 0 || EPI == 1) {
        // fp16 outputs: stage through smem for 16B-coalesced stores.
        // Stage: 32 rows x 136 halves (272B stride: 4-bank row rotation).
        __half* sC = dsm;
        const int srow = wm * 16 + gid;
        const int scol = wn * 32 + 2 * tig;
        #pragma unroll
        for (int mt = 0; mt < 4; mt++) {
            __syncthreads();   // stage free (main loop drained / prev mt stored)
            #pragma unroll
            for (int nt = 0; nt < 4; nt++) {
                int cb = n0 + wn * 32 + nt * 8 + 2 * tig;
                float bs0 = bias[cb], bs1 = bias[cb + 1];
                float v00 = c[mt][nt][0] + bs0, v01 = c[mt][nt][1] + bs1;
                float v10 = c[mt][nt][2] + bs0, v11 = c[mt][nt][3] + bs1;
                if (EPI == 0) {
                    if (cb < 256) { v00 *= SCALE; v01 *= SCALE; v10 *= SCALE; v11 *= SCALE; }
                } else {
                    const float kk = 0.70710678118654752f;
                    v00 = 0.5f * v00 * (1.f + erff(v00 * kk));
                    v01 = 0.5f * v01 * (1.f + erff(v01 * kk));
                    v10 = 0.5f * v10 * (1.f + erff(v10 * kk));
                    v11 = 0.5f * v11 * (1.f + erff(v11 * kk));
                }
                *(__half2*)&sC[(srow    ) * 136 + scol + nt * 8] = __floats2half2_rn(v00, v01);
                *(__half2*)&sC[(srow + 8) * 136 + scol + nt * 8] = __floats2half2_rn(v10, v11);
            }
            __syncthreads();
            #pragma unroll
            for (int s = 0; s < 2; s++) {
                int idx = tid + s * 256;
                int sr = idx >> 4, c8 = (idx & 15) * 8;
                int grow = m0 + (sr >> 4) * 64 + mt * 16 + (sr & 15);
                uint4 val = *(uint4*)&sC[sr * 136 + c8];
                *(uint4*)&Ch[(size_t)grow * Nn + n0 + c8] = val;
            }
        }
    } else {
        #pragma unroll
        for (int mt = 0; mt < 4; mt++) {
            #pragma unroll
            for (int nt = 0; nt < 4; nt++) {
                int r0 = m0 + wm * 64 + mt * 16 + gid;
                int r1 = r0 + 8;
                int cb = n0 + wn * 32 + nt * 8 + 2 * tig;
                float bs0 = bias[cb], bs1 = bias[cb + 1];
                float v00 = c[mt][nt][0] + bs0, v01 = c[mt][nt][1] + bs1;
                float v10 = c[mt][nt][2] + bs0, v11 = c[mt][nt][3] + bs1;

                if (EPI == 2) {
                    #pragma unroll
                    for (int rr = 0; rr < 2; rr++) {
                        int m = rr ? r1 : r0;
                        float va = rr ? v10 : v00, vb = rr ? v11 : v01;
                        int bw = m / NTOK, t = m % NTOK;
                        int b = bw >> 6, w = bw & 63;
                        int wh = w >> 3, ww = w & 7;
                        int r = t / 7, cc = t % 7;
                        int gh = wh * 7 + r + SHIFT; if (gh >= HW) gh -= HW;
                        int gw = ww * 7 + cc + SHIFT; if (gw >= HW) gw -= HW;
                        size_t dst = (size_t)(b * (HW*HW) + gh * HW + gw) * DIM + cb;
                        float2 rv = *(const float2*)&res[dst];
                        *(float2*)&Cf[dst] = make_float2(va + rv.x, vb + rv.y);
                    }
                } else {
                    size_t d0 = (size_t)r0 * Nn + cb, d1 = (size_t)r1 * Nn + cb;
                    float2 ra = *(const float2*)&res[d0];
                    float2 rb2 = *(const float2*)&res[d1];
                    *(float2*)&Cf[d0] = make_float2(v00 + ra.x, v01 + ra.y);
                    *(float2*)&Cf[d1] = make_float2(v10 + rb2.x, v11 + rb2.y);
                }
            }
        }
    }
}

// ---------------- tensor-core attention (masked-bias table, sP overlay) ----
__global__ void __launch_bounds__(256) attn_kernel(
    const __half* __restrict__ qkv, const __half* __restrict__ biasM,
    __half* __restrict__ out)
{
    __shared__ __half sQ [64][40];
    __shared__ __half sK [56][40];
    __shared__ __half sVT[32][72];
    __shared__ float  sS [64][60];

    __half (*sP)[120] = reinterpret_cast<__half(*)[120]>(sS);

    const int bw = blockIdx.x >> 3;
    const int h  = blockIdx.x & 7;
    const int tid = threadIdx.x, lane = tid & 31, wid = tid >> 5;
    const int gid = lane >> 2, tig = lane & 3;

    const int w = bw & 63;
    const int type = (((w >> 3) == 7) ? 2 : 0) + (((w & 7) == 7) ? 1 : 0);
    const __half* bm = biasM + ((size_t)(type * NH + h)) * (NTOK * NTOK);

    for (int i = tid; i < 32 * 36; i += 256) ((uint32_t*)sVT)[i] = 0;

    for (int i = tid; i < NTOK * 4; i += 256) {
        int n = i >> 2, d8 = (i & 3) * 8;
        size_t basep = (size_t)(bw * NTOK + n) * 768 + h * HD + d8;
        uint4 qu = *(const uint4*)&qkv[basep];
        uint4 ku = *(const uint4*)&qkv[basep + 256];
        uint4 vu = *(const uint4*)&qkv[basep + 512];
        *(uint4*)&sQ[n][d8] = qu;
        *(uint4*)&sK[n][d8] = ku;
        const __half* vh = (const __half*)&vu;
        #pragma unroll
        for (int j = 0; j < 8; j++) sVT[d8 + j][n] = vh[j];
    }
    __syncthreads();

    for (int t = wid; t < 28; t += 8) {
        int mt = t & 3, nt = t >> 2;
        int rb = mt * 16, nb = nt * 8;
        float c[4] = {0.f, 0.f, 0.f, 0.f};
        const uint32_t* qr0 = (const uint32_t*)&sQ[rb + gid][0];
        const uint32_t* qr1 = (const uint32_t*)&sQ[rb + gid + 8][0];
        const uint32_t* kr  = (const uint32_t*)&sK[nb + gid][0];
        #pragma unroll
        for (int ks = 0; ks < 2; ks++) {
            unsigned a[4] = { qr0[8*ks + tig], qr1[8*ks + tig],
                              qr0[8*ks + tig + 4], qr1[8*ks + tig + 4] };
            unsigned b[2] = { kr[8*ks + tig], kr[8*ks + tig + 4] };
            mma_f16(c, a, b);
        }
        sS[rb + gid    ][nb + 2*tig]     = c[0];
        sS[rb + gid    ][nb + 2*tig + 1] = c[1];
        sS[rb + gid + 8][nb + 2*tig]     = c[2];
        sS[rb + gid + 8][nb + 2*tig + 1] = c[3];
    }
    __syncthreads();

    bool has1 = lane < (NTOK - 32);
    int m1c = has1 ? lane + 32 : lane;

    for (int n = wid; n < NTOK; n += 8) {
        float a0 = sS[n][lane] + __half2float(bm[n * NTOK + lane]);
        float a1 = has1 ? (sS[n][m1c] + __half2float(bm[n * NTOK + m1c])) : -1e30f;

        float mx = fmaxf(a0, a1);
        #pragma unroll
        for (int o = 16; o > 0; o >>= 1) mx = fmaxf(mx, __shfl_xor_sync(0xFFFFFFFFu, mx, o));
        float e0 = __expf(a0 - mx);
        float e1 = has1 ? __expf(a1 - mx) : 0.f;
        float sm = e0 + e1;
        #pragma unroll
        for (int o = 16; o > 0; o >>= 1) sm += __shfl_xor_sync(0xFFFFFFFFu, sm, o);
        float inv = 1.f / sm;
        __syncwarp();
        sP[n][lane]      = __float2half(e0 * inv);
        sP[n][lane + 32] = has1 ? __float2half(e1 * inv) : __half(0.f);
    }
    __syncthreads();

    for (int t = wid; t < 16; t += 8) {
        int mt = t & 3, nt = t >> 2;
        int rb = mt * 16, nb = nt * 8;
        float c[4] = {0.f, 0.f, 0.f, 0.f};
        const uint32_t* pr0 = (const uint32_t*)&sP[rb + gid][0];
        const uint32_t* pr1 = (const uint32_t*)&sP[rb + gid + 8][0];
        const uint32_t* vr  = (const uint32_t*)&sVT[nb + gid][0];
        #pragma unroll
        for (int ks = 0; ks < 4; ks++) {
            unsigned a[4] = { pr0[8*ks + tig], pr1[8*ks + tig],
                              pr0[8*ks + tig + 4], pr1[8*ks + tig + 4] };
            unsigned b[2] = { vr[8*ks + tig], vr[8*ks + tig + 4] };
            mma_f16(c, a, b);
        }
        int n0 = rb + gid, n1 = n0 + 8;
        int d = nb + 2 * tig;
        if (n0 < NTOK)
            *(__half2*)&out[(size_t)(bw * NTOK + n0) * 256 + h * HD + d] =
                __floats2half2_rn(c[0], c[1]);
        if (n1 < NTOK)
            *(__half2*)&out[(size_t)(bw * NTOK + n1) * 256 + h * HD + d] =
                __floats2half2_rn(c[2], c[3]);
    }
}

// ---------------- launcher ----------------
extern "C" void kernel_launch(void* const* d_in, const int* in_sizes, int n_in,
                              void* d_out, int out_size)
{
    (void)in_sizes; (void)n_in; (void)out_size;
    const float* x        = (const float*)d_in[0];
    const float* norm1_g  = (const float*)d_in[1];
    const float* norm1_b  = (const float*)d_in[2];
    const float* qkv_w    = (const float*)d_in[3];
    const float* qkv_b    = (const float*)d_in[4];
    const float* rel_tab  = (const float*)d_in[5];
    const float* proj_w   = (const float*)d_in[6];
    const float* proj_b   = (const float*)d_in[7];
    const float* norm2_g  = (const float*)d_in[8];
    const float* norm2_b  = (const float*)d_in[9];
    const float* fc1_w    = (const float*)d_in[10];
    const float* fc1_b    = (const float*)d_in[11];
    const float* fc2_w    = (const float*)d_in[12];
    const float* fc2_b    = (const float*)d_in[13];
    float* out = (float*)d_out;

    __half *p_a, *p_qkv, *p_h1, *p_wqkv, *p_wproj, *p_wfc1, *p_wfc2, *p_biasM;
    float *p_xres;
    cudaGetSymbolAddress((void**)&p_a,     hb_a);
    cudaGetSymbolAddress((void**)&p_qkv,   hb_qkv);
    cudaGetSymbolAddress((void**)&p_h1,    hb_h1);
    cudaGetSymbolAddress((void**)&p_xres,  g_xres);
    cudaGetSymbolAddress((void**)&p_biasM, g_biasM);
    cudaGetSymbolAddress((void**)&p_wqkv,  hw_qkv);
    cudaGetSymbolAddress((void**)&p_wproj, hw_proj);
    cudaGetSymbolAddress((void**)&p_wfc1,  hw_fc1);
    cudaGetSymbolAddress((void**)&p_wfc2,  hw_fc2);

    cudaFuncSetAttribute(hgemm<0>, cudaFuncAttributeMaxDynamicSharedMemorySize, GSMEM);
    cudaFuncSetAttribute(hgemm<1>, cudaFuncAttributeMaxDynamicSharedMemorySize, GSMEM);
    cudaFuncSetAttribute(hgemm<2>, cudaFuncAttributeMaxDynamicSharedMemorySize, GSMEM);
    cudaFuncSetAttribute(hgemm<3>, cudaFuncAttributeMaxDynamicSharedMemorySize, GSMEM);

    const int M = MTOK;

    wconv_kernel<<<(768*256 + 256*256 + 255)/256, 256>>>(qkv_w, p_wqkv, 768*256,
                                                         proj_w, p_wproj, 256*256);
    wconv_kernel<<<(1024*256 + 256*1024 + 255)/256, 256>>>(fc1_w, p_wfc1, 1024*256,
                                                           fc2_w, p_wfc2, 256*1024);
    biasm_kernel<<<(4*NH*NTOK*NTOK + 255)/256, 256>>>(rel_tab, p_biasM);
    ln_kernel<1><<<M/8, 256>>>(x, p_a, norm1_g, norm1_b);
    // slot #5 (profiled): qkv gemm
    hgemm<0><<<dim3(768/128, M/128), 256, GSMEM>>>(p_a, p_wqkv, qkv_b, nullptr, p_qkv, nullptr, M, 768, 256);
    attn_kernel<<<BW * NH, 256>>>(p_qkv, p_biasM, p_a);
    hgemm<2><<<dim3(256/128, M/128), 256, GSMEM>>>(p_a, p_wproj, proj_b, p_xres, nullptr, x, M, 256, 256);
    ln_kernel<0><<<M/8, 256>>>(p_xres, p_a, norm2_g, norm2_b);
    hgemm<1><<<dim3(1024/128, M/128), 256, GSMEM>>>(p_a, p_wfc1, fc1_b, nullptr, p_h1, nullptr, M, 1024, 256);
    hgemm<3><<<dim3(256/128, M/128), 256, GSMEM>>>(p_h1, p_wfc2, fc2_b, out, nullptr, p_xres, M, 256, 1024);
}

// round 12
// speedup vs baseline: 1.1782x; 1.0725x over previous
#include <cuda_runtime.h>
#include <cuda_fp16.h>
#include <math.h>
#include <stdint.h>

// ---------------- problem constants ----------------
#define BATCH   32
#define HW      56
#define DIM     256
#define WS      7
#define SHIFT   3
#define NH      8
#define HD      32
#define NTOK    49
#define NWIN    64
#define BW      (BATCH*NWIN)
#define MTOK    (BATCH*HW*HW)   // 100352
#define SCALE   0.17677669529663687f

// ---------------- scratch ----------------
__device__ __half hb_a  [(size_t)MTOK * 256];
__device__ __half hb_qkv[(size_t)MTOK * 768];
__device__ __half hb_h1 [(size_t)MTOK * 1024];
__device__ float  g_xres[(size_t)MTOK * 256];
__device__ __half g_biasM[4 * NH * NTOK * NTOK];
__device__ __half hw_qkv [768 * 256];
__device__ __half hw_proj[256 * 256];
__device__ __half hw_fc1 [1024 * 256];
__device__ __half hw_fc2 [256 * 1024];

// ---------------- PTX helpers ----------------
__device__ __forceinline__ uint32_t cvta_s(const void* p) {
    uint32_t a;
    asm("{ .reg .u64 t; cvta.to.shared.u64 t, %1; cvt.u32.u64 %0, t; }" : "=r"(a) : "l"(p));
    return a;
}
__device__ __forceinline__ void ldsm_x4(unsigned* r, uint32_t a) {
    asm volatile("ldmatrix.sync.aligned.m8n8.x4.shared.b16 {%0,%1,%2,%3}, [%4];"
        : "=r"(r[0]), "=r"(r[1]), "=r"(r[2]), "=r"(r[3]) : "r"(a));
}
#define CP_ASYNC16(dst, src) asm volatile("cp.async.ca.shared.global [%0], [%1], 16;" :: "r"(dst), "l"(src))
#define CP_COMMIT()          asm volatile("cp.async.commit_group;" ::: "memory")
#define CP_WAIT1()           asm volatile("cp.async.wait_group 1;" ::: "memory")
#define CP_WAIT0()           asm volatile("cp.async.wait_group 0;" ::: "memory")

__device__ __forceinline__ void mma_f16(float* c, const unsigned* a, const unsigned* b) {
    asm("mma.sync.aligned.m16n8k16.row.col.f32.f16.f16.f32 "
        "{%0,%1,%2,%3},{%4,%5,%6,%7},{%8,%9},{%0,%1,%2,%3};"
        : "+f"(c[0]), "+f"(c[1]), "+f"(c[2]), "+f"(c[3])
        : "r"(a[0]), "r"(a[1]), "r"(a[2]), "r"(a[3]), "r"(b[0]), "r"(b[1]));
}

// ---------------- weight fp32 -> fp16 ----------------
__global__ void wconv_kernel(const float* __restrict__ w0, __half* __restrict__ o0, int n0,
                             const float* __restrict__ w1, __half* __restrict__ o1, int n1)
{
    int i = blockIdx.x * 256 + threadIdx.x;
    if (i < n0) o0[i] = __float2half(w0[i]);
    else if (i < n0 + n1) o1[i - n0] = __float2half(w1[i - n0]);
}

// ---------------- masked rel-pos bias table ----------------
__global__ void biasm_kernel(const float* __restrict__ rel_table, __half* __restrict__ bm)
{
    int i = blockIdx.x * 256 + threadIdx.x;
    if (i >= 4 * NH * NTOK * NTOK) return;
    int type = i / (NH * NTOK * NTOK);
    int rem  = i % (NH * NTOK * NTOK);
    int h = rem / (NTOK * NTOK);
    int s = rem % (NTOK * NTOK);
    int n = s / NTOK, m = s % NTOK;
    int rn = n / 7, cn = n % 7, rm = m / 7, cm = m % 7;
    int idx = (rn - rm + 6) * 13 + (cn - cm + 6);
    float v = rel_table[idx * NH + h];
    int th = type >> 1, tw = type & 1;
    int rhn = th ? (rn < 4 ? 1 : 2) : 0;
    int rwn = tw ? (cn < 4 ? 1 : 2) : 0;
    int rhm = th ? (rm < 4 ? 1 : 2) : 0;
    int rwm = tw ? (cm < 4 ? 1 : 2) : 0;
    if (rhn * 3 + rwn != rhm * 3 + rwm) v -= 100.f;
    bm[i] = __float2half(v);
}

// ---------------- LayerNorm: one row per warp, float4 I/O ----------------
template<int PERM>
__global__ void __launch_bounds__(256) ln_kernel(
    const float* __restrict__ in, __half* __restrict__ out,
    const float* __restrict__ gam, const float* __restrict__ bet)
{
    const int row = blockIdx.x * 8 + (threadIdx.x >> 5);
    const int lane = threadIdx.x & 31;
    int src;
    if (PERM) {
        int bw = row / NTOK, t = row % NTOK;
        int b = bw >> 6, w = bw & 63;
        int wh = w >> 3, ww = w & 7;
        int r = t / 7, c = t % 7;
        int gh = wh * 7 + r + SHIFT; if (gh >= HW) gh -= HW;
        int gw = ww * 7 + c + SHIFT; if (gw >= HW) gw -= HW;
        src = (b * (HW*HW) + gh * HW + gw) * DIM;
    } else {
        src = row * DIM;
    }
    const int col = lane * 8;
    float4 v0 = *(const float4*)&in[src + col];
    float4 v1 = *(const float4*)&in[src + col + 4];

    float s = v0.x+v0.y+v0.z+v0.w + v1.x+v1.y+v1.z+v1.w;
    float q = v0.x*v0.x+v0.y*v0.y+v0.z*v0.z+v0.w*v0.w
            + v1.x*v1.x+v1.y*v1.y+v1.z*v1.z+v1.w*v1.w;
    #pragma unroll
    for (int o = 16; o > 0; o >>= 1) {
        s += __shfl_xor_sync(0xFFFFFFFFu, s, o);
        q += __shfl_xor_sync(0xFFFFFFFFu, q, o);
    }
    float mu = s * (1.0f/DIM);
    float rstd = rsqrtf(q * (1.0f/DIM) - mu*mu + 1e-5f);

    float4 g0 = *(const float4*)&gam[col], g1 = *(const float4*)&gam[col+4];
    float4 b0 = *(const float4*)&bet[col], b1 = *(const float4*)&bet[col+4];

    uint4 o8;
    ((__half2*)&o8)[0] = __floats2half2_rn((v0.x-mu)*rstd*g0.x+b0.x, (v0.y-mu)*rstd*g0.y+b0.y);
    ((__half2*)&o8)[1] = __floats2half2_rn((v0.z-mu)*rstd*g0.z+b0.z, (v0.w-mu)*rstd*g0.w+b0.w);
    ((__half2*)&o8)[2] = __floats2half2_rn((v1.x-mu)*rstd*g1.x+b1.x, (v1.y-mu)*rstd*g1.y+b1.y);
    ((__half2*)&o8)[3] = __floats2half2_rn((v1.z-mu)*rstd*g1.z+b1.z, (v1.w-mu)*rstd*g1.w+b1.w);
    *(uint4*)&out[(size_t)row * DIM + col] = o8;
}

// ---------------- fp16 GEMM: 4 warps, warp tile 64x64, cp.async 3-stage ----
#define STG_H    (128 * 40)
#define STG_B    (STG_H * 2)
#define GSMEM    (6 * STG_B)   // 61440 B

template<int EPI>
__global__ void __launch_bounds__(128, 2) hgemm(
    const __half* __restrict__ A, const __half* __restrict__ B,
    const float* __restrict__ bias, float* __restrict__ Cf, __half* __restrict__ Ch,
    const float* __restrict__ res, int M, int Nn, int K)
{
    extern __shared__ __half dsm[];

    const int tid = threadIdx.x;
    const int lane = tid & 31, wid = tid >> 5;
    const int wm = wid >> 1, wn = wid & 1;      // 2x2 warps, tile 64x64
    const int gid = lane >> 2, tig = lane & 3;
    const int m0 = blockIdx.y * 128, n0 = blockIdx.x * 128;

    const uint32_t sbase = cvta_s(dsm);
    const uint32_t sA = sbase;
    const uint32_t sB = sbase + 3 * STG_B;

    const int lr0 = tid >> 2, lq0 = tid & 3;    // loader: 32 rows x 4 quads, x4 row-steps

    float c[4][8][4];
    #pragma unroll
    for (int i = 0; i < 4; i++)
        #pragma unroll
        for (int j = 0; j < 8; j++)
            #pragma unroll
            for (int r = 0; r < 4; r++) c[i][j][r] = 0.f;

    const int nk = K >> 5;

    // A frags: row = wm*64 + mt*16 + (lane&15), col = kk*16 + (lane>>4)*8
    const uint32_t a_off = ((uint32_t)(wm * 64 + (lane & 15)) * 40 + (lane >> 4) * 8) * 2;
    // B frags (x4 over nt-pair p): row = wn*64 + p*16 + ((lane>>4)&1)*8 + (lane&7)
    const uint32_t b_off = ((uint32_t)(wn * 64 + ((lane >> 4) & 1) * 8 + (lane & 7)) * 40
                           + ((lane >> 3) & 1) * 8) * 2;

    auto issue = [&](int kt, int stg) {
        const size_t kb = (size_t)kt * 32 + lq0 * 8;
        #pragma unroll
        for (int s = 0; s < 4; s++) {
            int row = lr0 + 32 * s;
            uint32_t dA = sA + stg * STG_B + (row * 40 + lq0 * 8) * 2;
            uint32_t dB = sB + stg * STG_B + (row * 40 + lq0 * 8) * 2;
            CP_ASYNC16(dA, &A[(size_t)(m0 + row) * K + kb]);
            CP_ASYNC16(dB, &B[(size_t)(n0 + row) * K + kb]);
        }
        CP_COMMIT();
    };

    issue(0, 0);
    issue(1, 1);

    for (int kt = 0; kt < nk; kt++) {
        const int stg = kt % 3;
        if (kt + 2 < nk) { CP_WAIT1(); } else { CP_WAIT0(); }
        __syncthreads();
        if (kt + 2 < nk) issue(kt + 2, (kt + 2) % 3);

        const uint32_t aS = sA + stg * STG_B + a_off;
        const uint32_t bS = sB + stg * STG_B + b_off;
        #pragma unroll
        for (int kk = 0; kk < 2; kk++) {
            unsigned af[4][4], bf[8][2];
            #pragma unroll
            for (int mt = 0; mt < 4; mt++)
                ldsm_x4(af[mt], aS + (mt * 16 * 40 + kk * 16) * 2);
            #pragma unroll
            for (int p = 0; p < 4; p++) {
                unsigned br[4];
                ldsm_x4(br, bS + (p * 16 * 40 + kk * 16) * 2);
                bf[2*p][0]   = br[0]; bf[2*p][1]   = br[1];
                bf[2*p+1][0] = br[2]; bf[2*p+1][1] = br[3];
            }
            #pragma unroll
            for (int mt = 0; mt < 4; mt++)
                #pragma unroll
                for (int nt = 0; nt < 8; nt++)
                    mma_f16(c[mt][nt], af[mt], bf[nt]);
        }
    }

    // ---------------- epilogue ----------------
    if (EPI == 0 || EPI == 1) {
        // fp16 outputs staged through smem: 32 rows x 136 halves per mt slice.
        __half* sC = dsm;
        const int srow = wm * 16 + gid;
        const int scol = wn * 64 + 2 * tig;
        #pragma unroll
        for (int mt = 0; mt < 4; mt++) {
            __syncthreads();
            #pragma unroll
            for (int nt = 0; nt < 8; nt++) {
                int cb = n0 + wn * 64 + nt * 8 + 2 * tig;
                float bs0 = bias[cb], bs1 = bias[cb + 1];
                float v00 = c[mt][nt][0] + bs0, v01 = c[mt][nt][1] + bs1;
                float v10 = c[mt][nt][2] + bs0, v11 = c[mt][nt][3] + bs1;
                if (EPI == 0) {
                    if (cb < 256) { v00 *= SCALE; v01 *= SCALE; v10 *= SCALE; v11 *= SCALE; }
                } else {
                    const float kk = 0.70710678118654752f;
                    v00 = 0.5f * v00 * (1.f + erff(v00 * kk));
                    v01 = 0.5f * v01 * (1.f + erff(v01 * kk));
                    v10 = 0.5f * v10 * (1.f + erff(v10 * kk));
                    v11 = 0.5f * v11 * (1.f + erff(v11 * kk));
                }
                *(__half2*)&sC[(srow    ) * 136 + scol + nt * 8] = __floats2half2_rn(v00, v01);
                *(__half2*)&sC[(srow + 8) * 136 + scol + nt * 8] = __floats2half2_rn(v10, v11);
            }
            __syncthreads();
            #pragma unroll
            for (int s = 0; s < 4; s++) {
                int idx = tid + s * 128;
                int sr = idx >> 4, c8 = (idx & 15) * 8;
                int grow = m0 + (sr >> 4) * 64 + mt * 16 + (sr & 15);
                uint4 val = *(uint4*)&sC[sr * 136 + c8];
                *(uint4*)&Ch[(size_t)grow * Nn + n0 + c8] = val;
            }
        }
    } else {
        #pragma unroll
        for (int mt = 0; mt < 4; mt++) {
            #pragma unroll
            for (int nt = 0; nt < 8; nt++) {
                int r0 = m0 + wm * 64 + mt * 16 + gid;
                int r1 = r0 + 8;
                int cb = n0 + wn * 64 + nt * 8 + 2 * tig;
                float bs0 = bias[cb], bs1 = bias[cb + 1];
                float v00 = c[mt][nt][0] + bs0, v01 = c[mt][nt][1] + bs1;
                float v10 = c[mt][nt][2] + bs0, v11 = c[mt][nt][3] + bs1;

                if (EPI == 2) {
                    #pragma unroll
                    for (int rr = 0; rr < 2; rr++) {
                        int m = rr ? r1 : r0;
                        float va = rr ? v10 : v00, vb = rr ? v11 : v01;
                        int bw = m / NTOK, t = m % NTOK;
                        int b = bw >> 6, w = bw & 63;
                        int wh = w >> 3, ww = w & 7;
                        int r = t / 7, cc = t % 7;
                        int gh = wh * 7 + r + SHIFT; if (gh >= HW) gh -= HW;
                        int gw = ww * 7 + cc + SHIFT; if (gw >= HW) gw -= HW;
                        size_t dst = (size_t)(b * (HW*HW) + gh * HW + gw) * DIM + cb;
                        float2 rv = *(const float2*)&res[dst];
                        *(float2*)&Cf[dst] = make_float2(va + rv.x, vb + rv.y);
                    }
                } else {
                    size_t d0 = (size_t)r0 * Nn + cb, d1 = (size_t)r1 * Nn + cb;
                    float2 ra = *(const float2*)&res[d0];
                    float2 rb2 = *(const float2*)&res[d1];
                    *(float2*)&Cf[d0] = make_float2(v00 + ra.x, v01 + ra.y);
                    *(float2*)&Cf[d1] = make_float2(v10 + rb2.x, v11 + rb2.y);
                }
            }
        }
    }
}

// ---------------- tensor-core attention (masked-bias table, sP overlay) ----
__global__ void __launch_bounds__(256) attn_kernel(
    const __half* __restrict__ qkv, const __half* __restrict__ biasM,
    __half* __restrict__ out)
{
    __shared__ __half sQ [64][40];
    __shared__ __half sK [56][40];
    __shared__ __half sVT[32][72];
    __shared__ float  sS [64][60];

    __half (*sP)[120] = reinterpret_cast<__half(*)[120]>(sS);

    const int bw = blockIdx.x >> 3;
    const int h  = blockIdx.x & 7;
    const int tid = threadIdx.x, lane = tid & 31, wid = tid >> 5;
    const int gid = lane >> 2, tig = lane & 3;

    const int w = bw & 63;
    const int type = (((w >> 3) == 7) ? 2 : 0) + (((w & 7) == 7) ? 1 : 0);
    const __half* bm = biasM + ((size_t)(type * NH + h)) * (NTOK * NTOK);

    for (int i = tid; i < 32 * 36; i += 256) ((uint32_t*)sVT)[i] = 0;

    for (int i = tid; i < NTOK * 4; i += 256) {
        int n = i >> 2, d8 = (i & 3) * 8;
        size_t basep = (size_t)(bw * NTOK + n) * 768 + h * HD + d8;
        uint4 qu = *(const uint4*)&qkv[basep];
        uint4 ku = *(const uint4*)&qkv[basep + 256];
        uint4 vu = *(const uint4*)&qkv[basep + 512];
        *(uint4*)&sQ[n][d8] = qu;
        *(uint4*)&sK[n][d8] = ku;
        const __half* vh = (const __half*)&vu;
        #pragma unroll
        for (int j = 0; j < 8; j++) sVT[d8 + j][n] = vh[j];
    }
    __syncthreads();

    for (int t = wid; t < 28; t += 8) {
        int mt = t & 3, nt = t >> 2;
        int rb = mt * 16, nb = nt * 8;
        float c[4] = {0.f, 0.f, 0.f, 0.f};
        const uint32_t* qr0 = (const uint32_t*)&sQ[rb + gid][0];
        const uint32_t* qr1 = (const uint32_t*)&sQ[rb + gid + 8][0];
        const uint32_t* kr  = (const uint32_t*)&sK[nb + gid][0];
        #pragma unroll
        for (int ks = 0; ks < 2; ks++) {
            unsigned a[4] = { qr0[8*ks + tig], qr1[8*ks + tig],
                              qr0[8*ks + tig + 4], qr1[8*ks + tig + 4] };
            unsigned b[2] = { kr[8*ks + tig], kr[8*ks + tig + 4] };
            mma_f16(c, a, b);
        }
        sS[rb + gid    ][nb + 2*tig]     = c[0];
        sS[rb + gid    ][nb + 2*tig + 1] = c[1];
        sS[rb + gid + 8][nb + 2*tig]     = c[2];
        sS[rb + gid + 8][nb + 2*tig + 1] = c[3];
    }
    __syncthreads();

    bool has1 = lane < (NTOK - 32);
    int m1c = has1 ? lane + 32 : lane;

    for (int n = wid; n < NTOK; n += 8) {
        float a0 = sS[n][lane] + __half2float(bm[n * NTOK + lane]);
        float a1 = has1 ? (sS[n][m1c] + __half2float(bm[n * NTOK + m1c])) : -1e30f;

        float mx = fmaxf(a0, a1);
        #pragma unroll
        for (int o = 16; o > 0; o >>= 1) mx = fmaxf(mx, __shfl_xor_sync(0xFFFFFFFFu, mx, o));
        float e0 = __expf(a0 - mx);
        float e1 = has1 ? __expf(a1 - mx) : 0.f;
        float sm = e0 + e1;
        #pragma unroll
        for (int o = 16; o > 0; o >>= 1) sm += __shfl_xor_sync(0xFFFFFFFFu, sm, o);
        float inv = 1.f / sm;
        __syncwarp();
        sP[n][lane]      = __float2half(e0 * inv);
        sP[n][lane + 32] = has1 ? __float2half(e1 * inv) : __half(0.f);
    }
    __syncthreads();

    for (int t = wid; t < 16; t += 8) {
        int mt = t & 3, nt = t >> 2;
        int rb = mt * 16, nb = nt * 8;
        float c[4] = {0.f, 0.f, 0.f, 0.f};
        const uint32_t* pr0 = (const uint32_t*)&sP[rb + gid][0];
        const uint32_t* pr1 = (const uint32_t*)&sP[rb + gid + 8][0];
        const uint32_t* vr  = (const uint32_t*)&sVT[nb + gid][0];
        #pragma unroll
        for (int ks = 0; ks < 4; ks++) {
            unsigned a[4] = { pr0[8*ks + tig], pr1[8*ks + tig],
                              pr0[8*ks + tig + 4], pr1[8*ks + tig + 4] };
            unsigned b[2] = { vr[8*ks + tig], vr[8*ks + tig + 4] };
            mma_f16(c, a, b);
        }
        int n0 = rb + gid, n1 = n0 + 8;
        int d = nb + 2 * tig;
        if (n0 < NTOK)
            *(__half2*)&out[(size_t)(bw * NTOK + n0) * 256 + h * HD + d] =
                __floats2half2_rn(c[0], c[1]);
        if (n1 < NTOK)
            *(__half2*)&out[(size_t)(bw * NTOK + n1) * 256 + h * HD + d] =
                __floats2half2_rn(c[2], c[3]);
    }
}

// ---------------- launcher ----------------
extern "C" void kernel_launch(void* const* d_in, const int* in_sizes, int n_in,
                              void* d_out, int out_size)
{
    (void)in_sizes; (void)n_in; (void)out_size;
    const float* x        = (const float*)d_in[0];
    const float* norm1_g  = (const float*)d_in[1];
    const float* norm1_b  = (const float*)d_in[2];
    const float* qkv_w    = (const float*)d_in[3];
    const float* qkv_b    = (const float*)d_in[4];
    const float* rel_tab  = (const float*)d_in[5];
    const float* proj_w   = (const float*)d_in[6];
    const float* proj_b   = (const float*)d_in[7];
    const float* norm2_g  = (const float*)d_in[8];
    const float* norm2_b  = (const float*)d_in[9];
    const float* fc1_w    = (const float*)d_in[10];
    const float* fc1_b    = (const float*)d_in[11];
    const float* fc2_w    = (const float*)d_in[12];
    const float* fc2_b    = (const float*)d_in[13];
    float* out = (float*)d_out;

    __half *p_a, *p_qkv, *p_h1, *p_wqkv, *p_wproj, *p_wfc1, *p_wfc2, *p_biasM;
    float *p_xres;
    cudaGetSymbolAddress((void**)&p_a,     hb_a);
    cudaGetSymbolAddress((void**)&p_qkv,   hb_qkv);
    cudaGetSymbolAddress((void**)&p_h1,    hb_h1);
    cudaGetSymbolAddress((void**)&p_xres,  g_xres);
    cudaGetSymbolAddress((void**)&p_biasM, g_biasM);
    cudaGetSymbolAddress((void**)&p_wqkv,  hw_qkv);
    cudaGetSymbolAddress((void**)&p_wproj, hw_proj);
    cudaGetSymbolAddress((void**)&p_wfc1,  hw_fc1);
    cudaGetSymbolAddress((void**)&p_wfc2,  hw_fc2);

    cudaFuncSetAttribute(hgemm<0>, cudaFuncAttributeMaxDynamicSharedMemorySize, GSMEM);
    cudaFuncSetAttribute(hgemm<1>, cudaFuncAttributeMaxDynamicSharedMemorySize, GSMEM);
    cudaFuncSetAttribute(hgemm<2>, cudaFuncAttributeMaxDynamicSharedMemorySize, GSMEM);
    cudaFuncSetAttribute(hgemm<3>, cudaFuncAttributeMaxDynamicSharedMemorySize, GSMEM);

    const int M = MTOK;

    wconv_kernel<<<(768*256 + 256*256 + 255)/256, 256>>>(qkv_w, p_wqkv, 768*256,
                                                         proj_w, p_wproj, 256*256);
    wconv_kernel<<<(1024*256 + 256*1024 + 255)/256, 256>>>(fc1_w, p_wfc1, 1024*256,
                                                           fc2_w, p_wfc2, 256*1024);
    biasm_kernel<<<(4*NH*NTOK*NTOK + 255)/256, 256>>>(rel_tab, p_biasM);
    ln_kernel<1><<<M/8, 256>>>(x, p_a, norm1_g, norm1_b);
    hgemm<0><<<dim3(768/128, M/128), 128, GSMEM>>>(p_a, p_wqkv, qkv_b, nullptr, p_qkv, nullptr, M, 768, 256);
    attn_kernel<<<BW * NH, 256>>>(p_qkv, p_biasM, p_a);
    hgemm<2><<<dim3(256/128, M/128), 128, GSMEM>>>(p_a, p_wproj, proj_b, p_xres, nullptr, x, M, 256, 256);
    ln_kernel<0><<<M/8, 256>>>(p_xres, p_a, norm2_g, norm2_b);
    hgemm<1><<<dim3(1024/128, M/128), 128, GSMEM>>>(p_a, p_wfc1, fc1_b, nullptr, p_h1, nullptr, M, 1024, 256);
    hgemm<3><<<dim3(256/128, M/128), 128, GSMEM>>>(p_h1, p_wfc2, fc2_b, out, nullptr, p_xres, M, 256, 1024);
}